// round 2
// baseline (speedup 1.0000x reference)
#include <cuda_runtime.h>

// VectorQuantizer: x [N,256] fp32, emb [K,256] fp32.
// Outputs (flattened, fp32): quantized [N*256] | loss [1] | indices [N].
//
// distances = ||x||^2 - 2 x@emb.T + ||emb||^2 ; idx = argmin_k (first min)
// quantized_out = x + (emb[idx] - x)   (fp32 rounding replicated)
// loss = L + 0.25*L where L = mean((emb[idx]-x)^2) in fp32 structure.
//
// Rounding replication is load-bearing: distances sit on a ~1 ULP(256) grid,
// so we compute d = fl(fl(S - 2*M) + c) exactly as the reference formula does,
// with S = sequential fp32 sum of individually-rounded squares.

#define DIM  256
#define NMAX 65536
#define KMAX 4096
#define TM 64
#define TN 64
#define TD 16

__device__ float  g_S[NMAX];
__device__ float  g_c[KMAX];
__device__ int    g_idx[NMAX];
__device__ double g_acc;

// ---------------------------------------------------------------------------
// c[k] = sum_i fl(emb[k][i]^2), sequential fp32. Also zeroes the loss
// accumulator (once per launch/replay).
// ---------------------------------------------------------------------------
__global__ __launch_bounds__(256) void k_c(const float* __restrict__ emb, int K) {
    int k = blockIdx.x * blockDim.x + threadIdx.x;
    if (k == 0) g_acc = 0.0;
    if (k >= K) return;
    const float* e = emb + (size_t)k * DIM;
    float s = 0.0f;
    #pragma unroll 8
    for (int i = 0; i < DIM; i++) {
        s = __fadd_rn(s, __fmul_rn(e[i], e[i]));
    }
    g_c[k] = s;
}

// S[n] = sum_i fl(x[n][i]^2), sequential fp32 (hypothesis: matches ref order)
__global__ __launch_bounds__(256) void k_S(const float* __restrict__ x, int N) {
    int n = blockIdx.x * blockDim.x + threadIdx.x;
    if (n >= N) return;
    const float* row = x + (size_t)n * DIM;
    float s = 0.0f;
    #pragma unroll 8
    for (int i = 0; i < DIM; i++) {
        s = __fadd_rn(s, __fmul_rn(row[i], row[i]));
    }
    g_S[n] = s;
}

// ---------------------------------------------------------------------------
// Tiled fp32 GEMM (64 rows x 64 codes per tile) with fused per-row argmin.
// Ties broken by lowest code index (jnp.argmin semantics).
// ---------------------------------------------------------------------------
__global__ __launch_bounds__(256) void k_argmin(const float* __restrict__ x,
                                                const float* __restrict__ emb,
                                                int N, int K) {
    __shared__ float sx[TD][TM + 4];   // +4 pad keeps float4 rows 16B-aligned
    __shared__ float se[TD][TN + 4];
    __shared__ float sS[TM];
    __shared__ float sc[TN];
    __shared__ float cd[TM][16];
    __shared__ int   ci[TM][16];

    const int tid = threadIdx.x;
    const int tx  = tid & 15;
    const int ty  = tid >> 4;
    const int rb  = blockIdx.x * TM;

    const int lm  = tid >> 2;          // 0..63 : smem tile row loaded
    const int ld4 = (tid & 3) * 4;     // 0,4,8,12 : d-offset within stage

    if (tid < TM) sS[tid] = g_S[rb + tid];

    float bd = 3.402823466e38f;        // running best distance for row rb+tid
    int   bi = 0x7fffffff;

    for (int ct = 0; ct < K; ct += TN) {
        if (tid < TN) sc[tid] = g_c[ct + tid];

        float acc[4][4];
        #pragma unroll
        for (int i = 0; i < 4; i++)
            #pragma unroll
            for (int j = 0; j < 4; j++) acc[i][j] = 0.0f;

        for (int dt = 0; dt < DIM; dt += TD) {
            __syncthreads();
            {
                const float4 v = *reinterpret_cast<const float4*>(
                    x + (size_t)(rb + lm) * DIM + dt + ld4);
                sx[ld4 + 0][lm] = v.x; sx[ld4 + 1][lm] = v.y;
                sx[ld4 + 2][lm] = v.z; sx[ld4 + 3][lm] = v.w;
                const float4 w = *reinterpret_cast<const float4*>(
                    emb + (size_t)(ct + lm) * DIM + dt + ld4);
                se[ld4 + 0][lm] = w.x; se[ld4 + 1][lm] = w.y;
                se[ld4 + 2][lm] = w.z; se[ld4 + 3][lm] = w.w;
            }
            __syncthreads();
            #pragma unroll
            for (int d = 0; d < TD; d++) {
                const float4 a = *reinterpret_cast<const float4*>(&sx[d][ty * 4]);
                const float4 b = *reinterpret_cast<const float4*>(&se[d][tx * 4]);
                acc[0][0] = fmaf(a.x, b.x, acc[0][0]);
                acc[0][1] = fmaf(a.x, b.y, acc[0][1]);
                acc[0][2] = fmaf(a.x, b.z, acc[0][2]);
                acc[0][3] = fmaf(a.x, b.w, acc[0][3]);
                acc[1][0] = fmaf(a.y, b.x, acc[1][0]);
                acc[1][1] = fmaf(a.y, b.y, acc[1][1]);
                acc[1][2] = fmaf(a.y, b.z, acc[1][2]);
                acc[1][3] = fmaf(a.y, b.w, acc[1][3]);
                acc[2][0] = fmaf(a.z, b.x, acc[2][0]);
                acc[2][1] = fmaf(a.z, b.y, acc[2][1]);
                acc[2][2] = fmaf(a.z, b.z, acc[2][2]);
                acc[2][3] = fmaf(a.z, b.w, acc[2][3]);
                acc[3][0] = fmaf(a.w, b.x, acc[3][0]);
                acc[3][1] = fmaf(a.w, b.y, acc[3][1]);
                acc[3][2] = fmaf(a.w, b.z, acc[3][2]);
                acc[3][3] = fmaf(a.w, b.w, acc[3][3]);
            }
        }

        // distances + per-thread argmin over its 4 codes (ascending index)
        #pragma unroll
        for (int i = 0; i < 4; i++) {
            const int   r  = ty * 4 + i;
            const float Sv = sS[r];
            float best = 3.402823466e38f;
            int   besti = 0x7fffffff;
            #pragma unroll
            for (int j = 0; j < 4; j++) {
                // d = fl(fl(S - 2*M) + c) : 2*M exact, FMA gives single rounding
                float t1   = __fmaf_rn(-2.0f, acc[i][j], Sv);
                float dist = __fadd_rn(t1, sc[tx * 4 + j]);
                int   kidx = ct + tx * 4 + j;
                if (dist < best) { best = dist; besti = kidx; }
            }
            cd[r][tx] = best;
            ci[r][tx] = besti;
        }
        __syncthreads();
        if (tid < TM) {
            #pragma unroll
            for (int t = 0; t < 16; t++) {
                float dcand = cd[tid][t];
                int   icand = ci[tid][t];
                if (dcand < bd || (dcand == bd && icand < bi)) {
                    bd = dcand; bi = icand;
                }
            }
        }
        __syncthreads();
    }

    if (tid < TM) g_idx[rb + tid] = bi;
}

// ---------------------------------------------------------------------------
// Epilogue: quantized = fl(x + fl(emb[idx]-x)), loss partials in fp64,
// indices as float.
// ---------------------------------------------------------------------------
__global__ __launch_bounds__(256) void k_epi(const float* __restrict__ x,
                                             const float* __restrict__ emb,
                                             float* __restrict__ out,
                                             float* __restrict__ outIdx,
                                             int N) {
    __shared__ double red[256];
    const int t = blockIdx.x * blockDim.x + threadIdx.x;
    const int nvec = N * (DIM / 4);
    double ls = 0.0;
    if (t < nvec) {
        const int n   = t >> 6;               // / (DIM/4)
        const int idx = g_idx[n];
        const float4 xv = reinterpret_cast<const float4*>(x)[t];
        const float4 ev = reinterpret_cast<const float4*>(emb)
                              [(size_t)idx * (DIM / 4) + (t & 63)];
        float d0 = __fsub_rn(ev.x, xv.x);
        float d1 = __fsub_rn(ev.y, xv.y);
        float d2 = __fsub_rn(ev.z, xv.z);
        float d3 = __fsub_rn(ev.w, xv.w);
        float4 o;
        o.x = __fadd_rn(xv.x, d0);
        o.y = __fadd_rn(xv.y, d1);
        o.z = __fadd_rn(xv.z, d2);
        o.w = __fadd_rn(xv.w, d3);
        reinterpret_cast<float4*>(out)[t] = o;
        ls  = (double)__fmul_rn(d0, d0) + (double)__fmul_rn(d1, d1)
            + (double)__fmul_rn(d2, d2) + (double)__fmul_rn(d3, d3);
        if (outIdx != nullptr && (t & 63) == 0) outIdx[n] = (float)idx;
    }
    red[threadIdx.x] = ls;
    __syncthreads();
    #pragma unroll
    for (int s = 128; s > 0; s >>= 1) {
        if (threadIdx.x < s) red[threadIdx.x] += red[threadIdx.x + s];
        __syncthreads();
    }
    if (threadIdx.x == 0) atomicAdd(&g_acc, red[0]);
}

__global__ void k_fin(float* __restrict__ out, int N) {
    double m = g_acc / ((double)N * (double)DIM);
    float L = (float)m;
    out[(size_t)N * DIM] = __fadd_rn(L, __fmul_rn(0.25f, L));
}

// ---------------------------------------------------------------------------
extern "C" void kernel_launch(void* const* d_in, const int* in_sizes, int n_in,
                              void* d_out, int out_size) {
    const float* x   = (const float*)d_in[0];
    const float* emb = (const float*)d_in[1];
    const int N = in_sizes[0] / DIM;   // 65536
    const int K = in_sizes[1] / DIM;   // 4096
    float* out = (float*)d_out;

    const long long Nq = (long long)N * DIM;
    const bool has_loss = (long long)out_size > Nq;
    const bool has_idx  = (long long)out_size >= Nq + 1 + N;
    float* outIdx = has_idx ? out + Nq + 1 : nullptr;

    k_c<<<(K + 255) / 256, 256>>>(emb, K);
    k_S<<<(N + 255) / 256, 256>>>(x, N);
    k_argmin<<<N / TM, 256>>>(x, emb, N, K);
    k_epi<<<(N * (DIM / 4) + 255) / 256, 256>>>(x, emb, out, outIdx, N);
    if (has_loss) k_fin<<<1, 1>>>(out, N);
}

// round 4
// speedup vs baseline: 3.1575x; 3.1575x over previous
#include <cuda_runtime.h>
#include <cuda_bf16.h>
#include <cstdint>
#include <cfloat>

// VectorQuantizer: x [N,256] fp32, emb [K,256] fp32.
// Out (fp32): quantized [N*256] | loss [1] | indices [N].
//
// Exact semantics (bit-matched in R2, rel_err=0):
//   S[n] = seq fp32 chain fadd(s, fmul(x,x));  c[k] same over emb
//   M    = seq fp32 fma chain over d
//   d    = fadd(fmaf(-2,M,S), c);  argmin, lowest-index ties
// Strategy: bf16 mma.sync prefilter (margin-safe) + exact-chain rescore.

#define DIM    256
#define NMAX   65536
#define KMAX   4096
#define CAP    128
#define MARGIN 2e-3f
#define BM     128
#define BN     128

__device__ __align__(16) float  g_S[NMAX];
__device__ __align__(16) float  g_c[KMAX];
__device__ int            g_idx[NMAX];
__device__ float          g_runmin[NMAX];
__device__ unsigned int   g_cnt[NMAX];
__device__ unsigned long long g_cand[(size_t)NMAX * CAP];
__device__ __align__(16) __nv_bfloat16 g_xb[(size_t)NMAX * DIM];
__device__ __align__(16) __nv_bfloat16 g_eb[(size_t)KMAX * DIM];
__device__ double         g_acc;

// ---------------------------------------------------------------------------
__global__ __launch_bounds__(256) void k_c(const float* __restrict__ emb, int K) {
    int k = blockIdx.x * blockDim.x + threadIdx.x;
    if (k == 0) g_acc = 0.0;
    if (k >= K) return;
    const float* e = emb + (size_t)k * DIM;
    float s = 0.0f;
    #pragma unroll 8
    for (int i = 0; i < DIM; i++) s = __fadd_rn(s, __fmul_rn(e[i], e[i]));
    g_c[k] = s;
}

__global__ __launch_bounds__(256) void k_S(const float* __restrict__ x, int N) {
    int n = blockIdx.x * blockDim.x + threadIdx.x;
    if (n >= N) return;
    g_cnt[n] = 0u;
    const float* row = x + (size_t)n * DIM;
    float s = 0.0f;
    #pragma unroll 8
    for (int i = 0; i < DIM; i++) s = __fadd_rn(s, __fmul_rn(row[i], row[i]));
    g_S[n] = s;
}

__global__ __launch_bounds__(256) void k_cvt_x(const float* __restrict__ s, int n4) {
    int i = blockIdx.x * blockDim.x + threadIdx.x;
    if (i >= n4) return;
    float4 v = ((const float4*)s)[i];
    __nv_bfloat162* d2 = (__nv_bfloat162*)g_xb;
    d2[2 * i + 0] = __floats2bfloat162_rn(v.x, v.y);
    d2[2 * i + 1] = __floats2bfloat162_rn(v.z, v.w);
}

__global__ __launch_bounds__(256) void k_cvt_e(const float* __restrict__ s, int n4) {
    int i = blockIdx.x * blockDim.x + threadIdx.x;
    if (i >= n4) return;
    float4 v = ((const float4*)s)[i];
    __nv_bfloat162* d2 = (__nv_bfloat162*)g_eb;
    d2[2 * i + 0] = __floats2bfloat162_rn(v.x, v.y);
    d2[2 * i + 1] = __floats2bfloat162_rn(v.z, v.w);
}

// ---------------------------------------------------------------------------
__device__ __forceinline__ void cpa16(uint32_t s, const void* g) {
    asm volatile("cp.async.cg.shared.global [%0], [%1], 16;\n" :: "r"(s), "l"(g));
}
__device__ __forceinline__ void ldsm4(uint32_t* r, uint32_t a) {
    asm volatile("ldmatrix.sync.aligned.m8n8.x4.shared.b16 {%0,%1,%2,%3}, [%4];"
        : "=r"(r[0]), "=r"(r[1]), "=r"(r[2]), "=r"(r[3]) : "r"(a));
}
__device__ __forceinline__ void mma16816(float* d, const uint32_t* a,
                                         uint32_t b0, uint32_t b1) {
    asm volatile("mma.sync.aligned.m16n8k16.row.col.f32.bf16.bf16.f32 "
        "{%0,%1,%2,%3}, {%4,%5,%6,%7}, {%8,%9}, {%0,%1,%2,%3};"
        : "+f"(d[0]), "+f"(d[1]), "+f"(d[2]), "+f"(d[3])
        : "r"(a[0]), "r"(a[1]), "r"(a[2]), "r"(a[3]), "r"(b0), "r"(b1));
}

#define SMEM_XS   0
#define SMEM_ES   (BM * 512)
#define SMEM_SC   (SMEM_ES + 2 * BN * 512)
#define SMEM_SS   (SMEM_SC + 2 * BN * 4)
#define SMEM_RM   (SMEM_SS + BM * 4)
#define SMEM_TOT  (SMEM_RM + BM * 4)

__global__ __launch_bounds__(256, 1) void k_gemm(int N, int K) {
    extern __shared__ char smem[];
    const uint32_t sb = (uint32_t)__cvta_generic_to_shared(smem);
    float* scf = (float*)(smem + SMEM_SC);
    float* sSf = (float*)(smem + SMEM_SS);
    int*   srm = (int*)  (smem + SMEM_RM);

    const int tid = threadIdx.x;
    const int rb  = blockIdx.x * BM;

    if (tid < BM) {
        srm[tid] = 0x7f7fffff;                 // +FLT_MAX bits
        sSf[tid] = g_S[rb + tid];
    }
    for (int i = tid; i < BM * 32; i += 256) {
        int r = i >> 5, c = i & 31;
        cpa16(sb + SMEM_XS + r * 512 + ((c ^ (r & 7)) << 4),
              g_xb + (size_t)(rb + r) * DIM + c * 8);
    }
    for (int i = tid; i < BN * 32; i += 256) {
        int r = i >> 5, c = i & 31;
        cpa16(sb + SMEM_ES + r * 512 + ((c ^ (r & 7)) << 4),
              g_eb + (size_t)r * DIM + c * 8);
    }
    if (tid < 32) cpa16(sb + SMEM_SC + tid * 16, g_c + tid * 4);
    asm volatile("cp.async.commit_group;\n");

    const int lane = tid & 31, wid = tid >> 5;
    const int mi = wid >> 1, ni = wid & 1;
    const int g = lane >> 2, t = lane & 3;
    const int nchunks = K / BN;

    for (int ci = 0; ci < nchunks; ci++) {
        const int buf = ci & 1;
        asm volatile("cp.async.wait_group 0;\n");
        __syncthreads();
        if (ci + 1 < nchunks) {
            const int nb = (ci + 1) & 1;
            for (int i = tid; i < BN * 32; i += 256) {
                int r = i >> 5, c = i & 31;
                cpa16(sb + SMEM_ES + nb * (BN * 512) + r * 512 + ((c ^ (r & 7)) << 4),
                      g_eb + (size_t)((ci + 1) * BN + r) * DIM + c * 8);
            }
            if (tid < 32) cpa16(sb + SMEM_SC + nb * 512 + tid * 16,
                                g_c + (ci + 1) * BN + tid * 4);
            asm volatile("cp.async.commit_group;\n");
        }

        float acc[2][8][4];
        #pragma unroll
        for (int mt = 0; mt < 2; mt++)
            #pragma unroll
            for (int nf = 0; nf < 8; nf++)
                #pragma unroll
                for (int q = 0; q < 4; q++) acc[mt][nf][q] = 0.0f;

        const uint32_t esb = sb + SMEM_ES + buf * (BN * 512);
        #pragma unroll
        for (int ks = 0; ks < 16; ks++) {
            uint32_t a[2][4];
            #pragma unroll
            for (int mt = 0; mt < 2; mt++) {
                int r = mi * 32 + mt * 16 + (lane & 7) + ((lane >> 3) & 1) * 8;
                ldsm4(a[mt], sb + SMEM_XS + r * 512 +
                             (((ks * 2 + (lane >> 4)) ^ (r & 7)) << 4));
            }
            uint32_t b[4][4];
            #pragma unroll
            for (int nq = 0; nq < 4; nq++) {
                int r = ni * 64 + nq * 16 + (lane & 7) + (lane >> 4) * 8;
                ldsm4(b[nq], esb + r * 512 +
                             (((ks * 2 + ((lane >> 3) & 1)) ^ (r & 7)) << 4));
            }
            #pragma unroll
            for (int mt = 0; mt < 2; mt++)
                #pragma unroll
                for (int nf = 0; nf < 8; nf++)
                    mma16816(acc[mt][nf], a[mt],
                             b[nf >> 1][(nf & 1) * 2 + 0],
                             b[nf >> 1][(nf & 1) * 2 + 1]);
        }

        const int cb = ci * BN;
        const float* scb = scf + buf * BN;

        // phase A: chunk-local running min into srm
        #pragma unroll
        for (int mt = 0; mt < 2; mt++) {
            #pragma unroll
            for (int h = 0; h < 2; h++) {
                const int rl = mi * 32 + mt * 16 + g + h * 8;
                const float S = sSf[rl];
                float lmin = FLT_MAX;
                #pragma unroll
                for (int nf = 0; nf < 8; nf++) {
                    #pragma unroll
                    for (int q = 0; q < 2; q++) {
                        float dist = __fadd_rn(
                            __fmaf_rn(-2.0f, acc[mt][nf][h * 2 + q], S),
                            scb[ni * 64 + nf * 8 + t * 2 + q]);
                        lmin = fminf(lmin, dist);
                    }
                }
                lmin = fminf(lmin, __shfl_xor_sync(0xffffffffu, lmin, 1));
                lmin = fminf(lmin, __shfl_xor_sync(0xffffffffu, lmin, 2));
                if (t == 0) atomicMin(&srm[rl], __float_as_int(lmin));
            }
        }
        __syncthreads();

        // phase B: append candidates within margin of post-chunk running min
        #pragma unroll
        for (int mt = 0; mt < 2; mt++) {
            #pragma unroll
            for (int h = 0; h < 2; h++) {
                const int rl = mi * 32 + mt * 16 + g + h * 8;
                const float S   = sSf[rl];
                const float rmw = __int_as_float(srm[rl]) + MARGIN;
                #pragma unroll
                for (int nf = 0; nf < 8; nf++) {
                    #pragma unroll
                    for (int q = 0; q < 2; q++) {
                        const int cl = ni * 64 + nf * 8 + t * 2 + q;
                        float dist = __fadd_rn(
                            __fmaf_rn(-2.0f, acc[mt][nf][h * 2 + q], S), scb[cl]);
                        if (dist <= rmw) {
                            unsigned int pos = atomicAdd(&g_cnt[rb + rl], 1u);
                            if (pos < CAP)
                                g_cand[(size_t)(rb + rl) * CAP + pos] =
                                    ((unsigned long long)__float_as_uint(dist) << 32)
                                    | (unsigned int)(cb + cl);
                        }
                    }
                }
            }
        }
    }
    __syncthreads();
    if (tid < BM) g_runmin[rb + tid] = __int_as_float(srm[tid]);
}

// ---------------------------------------------------------------------------
__device__ __forceinline__ unsigned long long exact_pack(
        const float* xr, const float* emb, float Sv, unsigned int k) {
    const float* er = emb + (size_t)k * DIM;
    float m = 0.0f;
    #pragma unroll 4
    for (int i = 0; i < 64; i++) {
        float4 xv = __ldg((const float4*)xr + i);
        float4 ev = __ldg((const float4*)er + i);
        m = __fmaf_rn(xv.x, ev.x, m);
        m = __fmaf_rn(xv.y, ev.y, m);
        m = __fmaf_rn(xv.z, ev.z, m);
        m = __fmaf_rn(xv.w, ev.w, m);
    }
    float d = __fadd_rn(__fmaf_rn(-2.0f, m, Sv), g_c[k]);
    return ((unsigned long long)__float_as_uint(d) << 32) | k;
}

__global__ __launch_bounds__(256) void k_rescore(const float* __restrict__ x,
                                                 const float* __restrict__ emb, int N) {
    const int w = (blockIdx.x * blockDim.x + threadIdx.x) >> 5;
    const int lane = threadIdx.x & 31;
    if (w >= N) return;
    const unsigned int cnt = g_cnt[w];
    if (cnt > CAP) return;
    const float thr = g_runmin[w] + MARGIN;
    const float Sv  = g_S[w];
    const float* xr = x + (size_t)w * DIM;
    unsigned long long best = 0xffffffffffffffffULL;
    for (unsigned int e = lane; e < cnt; e += 32) {
        unsigned long long ent = g_cand[(size_t)w * CAP + e];
        float dt = __uint_as_float((unsigned int)(ent >> 32));
        if (dt > thr) continue;
        unsigned long long v = exact_pack(xr, emb, Sv, (unsigned int)(ent & 0xffffffffu));
        if (v < best) best = v;
    }
    #pragma unroll
    for (int o = 16; o; o >>= 1) {
        unsigned long long v = __shfl_xor_sync(0xffffffffu, best, o);
        if (v < best) best = v;
    }
    if (lane == 0) g_idx[w] = (int)(best & 0xffffffffu);
}

__global__ __launch_bounds__(256) void k_fullscan(const float* __restrict__ x,
                                                  const float* __restrict__ emb,
                                                  int N, int K) {
    const int w = (blockIdx.x * blockDim.x + threadIdx.x) >> 5;
    const int lane = threadIdx.x & 31;
    if (w >= N) return;
    if (g_cnt[w] <= CAP) return;
    const float Sv  = g_S[w];
    const float* xr = x + (size_t)w * DIM;
    unsigned long long best = 0xffffffffffffffffULL;
    for (int k = lane; k < K; k += 32) {
        unsigned long long v = exact_pack(xr, emb, Sv, (unsigned int)k);
        if (v < best) best = v;
    }
    #pragma unroll
    for (int o = 16; o; o >>= 1) {
        unsigned long long v = __shfl_xor_sync(0xffffffffu, best, o);
        if (v < best) best = v;
    }
    if (lane == 0) g_idx[w] = (int)(best & 0xffffffffu);
}

// ---------------------------------------------------------------------------
__global__ __launch_bounds__(256) void k_epi(const float* __restrict__ x,
                                             const float* __restrict__ emb,
                                             float* __restrict__ out,
                                             float* __restrict__ outIdx, int N) {
    __shared__ double red[256];
    const int tno = blockIdx.x * blockDim.x + threadIdx.x;
    const int nvec = N * (DIM / 4);
    double ls = 0.0;
    if (tno < nvec) {
        const int n   = tno >> 6;
        const int idx = g_idx[n];
        const float4 xv = reinterpret_cast<const float4*>(x)[tno];
        const float4 ev = reinterpret_cast<const float4*>(emb)
                              [(size_t)idx * (DIM / 4) + (tno & 63)];
        float d0 = __fsub_rn(ev.x, xv.x), d1 = __fsub_rn(ev.y, xv.y);
        float d2 = __fsub_rn(ev.z, xv.z), d3 = __fsub_rn(ev.w, xv.w);
        float4 o;
        o.x = __fadd_rn(xv.x, d0); o.y = __fadd_rn(xv.y, d1);
        o.z = __fadd_rn(xv.z, d2); o.w = __fadd_rn(xv.w, d3);
        reinterpret_cast<float4*>(out)[tno] = o;
        ls = (double)__fmul_rn(d0, d0) + (double)__fmul_rn(d1, d1)
           + (double)__fmul_rn(d2, d2) + (double)__fmul_rn(d3, d3);
        if (outIdx != nullptr && (tno & 63) == 0) outIdx[n] = (float)idx;
    }
    red[threadIdx.x] = ls;
    __syncthreads();
    #pragma unroll
    for (int s = 128; s > 0; s >>= 1) {
        if (threadIdx.x < s) red[threadIdx.x] += red[threadIdx.x + s];
        __syncthreads();
    }
    if (threadIdx.x == 0) atomicAdd(&g_acc, red[0]);
}

__global__ void k_fin(float* __restrict__ out, int N) {
    double m = g_acc / ((double)N * (double)DIM);
    float L = (float)m;
    out[(size_t)N * DIM] = __fadd_rn(L, __fmul_rn(0.25f, L));
}

// ---------------------------------------------------------------------------
extern "C" void kernel_launch(void* const* d_in, const int* in_sizes, int n_in,
                              void* d_out, int out_size) {
    const float* x   = (const float*)d_in[0];
    const float* emb = (const float*)d_in[1];
    const int N = in_sizes[0] / DIM;
    const int K = in_sizes[1] / DIM;
    float* out = (float*)d_out;

    const long long Nq = (long long)N * DIM;
    const bool has_loss = (long long)out_size > Nq;
    const bool has_idx  = (long long)out_size >= Nq + 1 + N;
    float* outIdx = has_idx ? out + Nq + 1 : nullptr;

    cudaFuncSetAttribute(k_gemm, cudaFuncAttributeMaxDynamicSharedMemorySize,
                         SMEM_TOT);

    k_c<<<(K + 255) / 256, 256>>>(emb, K);
    k_S<<<(N + 255) / 256, 256>>>(x, N);
    k_cvt_x<<<(N * DIM / 4 + 255) / 256, 256>>>(x, N * DIM / 4);
    k_cvt_e<<<(K * DIM / 4 + 255) / 256, 256>>>(emb, K * DIM / 4);
    k_gemm<<<N / BM, 256, SMEM_TOT>>>(N, K);
    k_rescore<<<(N * 32 + 255) / 256, 256>>>(x, emb, N);
    k_fullscan<<<(N * 32 + 255) / 256, 256>>>(x, emb, N, K);
    k_epi<<<(N * (DIM / 4) + 255) / 256, 256>>>(x, emb, out, outIdx, N);
    if (has_loss) k_fin<<<1, 1>>>(out, N);
}